// round 3
// baseline (speedup 1.0000x reference)
#include <cuda_runtime.h>
#include <cuda_bf16.h>

// y = (x + 2) * 3 / 2 == fmaf(1.5f, x, 3.0f)
// HBM-bound streaming kernel. R3: persistent one-wave grid (no wave-transition
// overhead), block-stride tile loop, 8x float4 per thread front-batched,
// 32-bit indexing, streaming cache hints.

constexpr int VPT = 8;                 // float4 per thread
constexpr int THREADS = 256;
constexpr int TILE = VPT * THREADS;    // float4 per block-tile = 2048
constexpr int GRID = 152 * 6;          // GB300: 152 SMs x 6 resident blocks @40regs

__global__ void __launch_bounds__(THREADS) fma_stream_kernel(
    const float4* __restrict__ in, float4* __restrict__ out, unsigned ntiles)
{
    unsigned tid = threadIdx.x;
    for (unsigned t = blockIdx.x; t < ntiles; t += gridDim.x) {
        unsigned base = t * TILE + tid;

        float4 v[VPT];
#pragma unroll
        for (int k = 0; k < VPT; k++)
            v[k] = __ldcs(in + base + k * THREADS);

#pragma unroll
        for (int k = 0; k < VPT; k++) {
            float4 r;
            r.x = fmaf(1.5f, v[k].x, 3.0f);
            r.y = fmaf(1.5f, v[k].y, 3.0f);
            r.z = fmaf(1.5f, v[k].z, 3.0f);
            r.w = fmaf(1.5f, v[k].w, 3.0f);
            __stcs(out + base + k * THREADS, r);
        }
    }
}

// Generic remainder kernel (element granularity, any size).
__global__ void fma_tail_kernel(const float* __restrict__ in,
                                float* __restrict__ out,
                                long long start, long long n)
{
    long long i = start + (long long)blockIdx.x * blockDim.x + threadIdx.x;
    if (i < n) out[i] = fmaf(1.5f, in[i], 3.0f);
}

extern "C" void kernel_launch(void* const* d_in, const int* in_sizes, int n_in,
                              void* d_out, int out_size)
{
    const float* in = (const float*)d_in[0];
    float* out = (float*)d_out;
    long long n = (long long)in_sizes[0];

    long long n4 = n / 4;
    long long ntiles = n4 / TILE;
    if (ntiles > 0) {
        unsigned grid = (ntiles < GRID) ? (unsigned)ntiles : (unsigned)GRID;
        fma_stream_kernel<<<grid, THREADS>>>(
            (const float4*)in, (float4*)out, (unsigned)ntiles);
    }
    long long done = ntiles * (long long)TILE * 4;  // elements handled
    long long tail = n - done;
    if (tail > 0) {
        fma_tail_kernel<<<(unsigned)((tail + 255) / 256), 256>>>(
            in, out, done, n);
    }
}

// round 4
// speedup vs baseline: 1.1018x; 1.1018x over previous
#include <cuda_runtime.h>
#include <cuda_bf16.h>

// y = (x + 2) * 3 / 2 == fmaf(1.5f, x, 3.0f)
// HBM-bound streaming kernel. R4: flat grid (HW work-steal balances SM speed
// spread — persistent grid regressed in R3), VPT=16 float4 per thread with
// front-batched loads (MLP_p1=16), 32-bit indexing, streaming cache hints.

constexpr int VPT = 16;                // float4 per thread
constexpr int THREADS = 256;
constexpr int TILE = VPT * THREADS;    // float4 per block = 4096

__global__ void __launch_bounds__(THREADS) fma_stream_kernel(
    const float4* __restrict__ in, float4* __restrict__ out)
{
    unsigned base = blockIdx.x * TILE + threadIdx.x;

    float4 v[VPT];
#pragma unroll
    for (int k = 0; k < VPT; k++)
        v[k] = __ldcs(in + base + k * THREADS);

#pragma unroll
    for (int k = 0; k < VPT; k++) {
        float4 r;
        r.x = fmaf(1.5f, v[k].x, 3.0f);
        r.y = fmaf(1.5f, v[k].y, 3.0f);
        r.z = fmaf(1.5f, v[k].z, 3.0f);
        r.w = fmaf(1.5f, v[k].w, 3.0f);
        __stcs(out + base + k * THREADS, r);
    }
}

// Generic remainder kernel (element granularity, any size).
__global__ void fma_tail_kernel(const float* __restrict__ in,
                                float* __restrict__ out,
                                long long start, long long n)
{
    long long i = start + (long long)blockIdx.x * blockDim.x + threadIdx.x;
    if (i < n) out[i] = fmaf(1.5f, in[i], 3.0f);
}

extern "C" void kernel_launch(void* const* d_in, const int* in_sizes, int n_in,
                              void* d_out, int out_size)
{
    const float* in = (const float*)d_in[0];
    float* out = (float*)d_out;
    long long n = (long long)in_sizes[0];

    long long n4 = n / 4;
    long long full_blocks = n4 / TILE;
    if (full_blocks > 0) {
        fma_stream_kernel<<<(unsigned)full_blocks, THREADS>>>(
            (const float4*)in, (float4*)out);
    }
    long long done = full_blocks * (long long)TILE * 4;  // elements handled
    long long tail = n - done;
    if (tail > 0) {
        fma_tail_kernel<<<(unsigned)((tail + 255) / 256), 256>>>(
            in, out, done, n);
    }
}

// round 5
// speedup vs baseline: 1.1027x; 1.0008x over previous
#include <cuda_runtime.h>
#include <cuda_bf16.h>

// y = (x + 2) * 3 / 2 == fmaf(1.5f, x, 3.0f)
// HBM-bound streaming kernel. R5: R2 structure (flat grid, VPT=8, 256 thr,
// 32-bit idx, streaming hints) + 2-stage software pipeline: first half of
// stores issues while second half of loads is in flight, keeping the DRAM
// read/write mix steady instead of phase-alternating.

constexpr int VPT = 8;                 // float4 per thread
constexpr int HALF = VPT / 2;
constexpr int THREADS = 256;
constexpr int TILE = VPT * THREADS;    // float4 per block = 2048

__global__ void __launch_bounds__(THREADS) fma_stream_kernel(
    const float4* __restrict__ in, float4* __restrict__ out)
{
    unsigned base = blockIdx.x * TILE + threadIdx.x;

    // Stage 0: issue first-half loads.
    float4 a[HALF];
#pragma unroll
    for (int k = 0; k < HALF; k++)
        a[k] = __ldcs(in + base + k * THREADS);

    // Stage 1: issue second-half loads (independent — overlap with stage-0
    // returns), then drain stage-0 with fma+store while stage-1 is in flight.
    float4 b[HALF];
#pragma unroll
    for (int k = 0; k < HALF; k++)
        b[k] = __ldcs(in + base + (HALF + k) * THREADS);

#pragma unroll
    for (int k = 0; k < HALF; k++) {
        float4 r;
        r.x = fmaf(1.5f, a[k].x, 3.0f);
        r.y = fmaf(1.5f, a[k].y, 3.0f);
        r.z = fmaf(1.5f, a[k].z, 3.0f);
        r.w = fmaf(1.5f, a[k].w, 3.0f);
        __stcs(out + base + k * THREADS, r);
    }

#pragma unroll
    for (int k = 0; k < HALF; k++) {
        float4 r;
        r.x = fmaf(1.5f, b[k].x, 3.0f);
        r.y = fmaf(1.5f, b[k].y, 3.0f);
        r.z = fmaf(1.5f, b[k].z, 3.0f);
        r.w = fmaf(1.5f, b[k].w, 3.0f);
        __stcs(out + base + (HALF + k) * THREADS, r);
    }
}

// Generic remainder kernel (element granularity, any size).
__global__ void fma_tail_kernel(const float* __restrict__ in,
                                float* __restrict__ out,
                                long long start, long long n)
{
    long long i = start + (long long)blockIdx.x * blockDim.x + threadIdx.x;
    if (i < n) out[i] = fmaf(1.5f, in[i], 3.0f);
}

extern "C" void kernel_launch(void* const* d_in, const int* in_sizes, int n_in,
                              void* d_out, int out_size)
{
    const float* in = (const float*)d_in[0];
    float* out = (float*)d_out;
    long long n = (long long)in_sizes[0];

    long long n4 = n / 4;
    long long full_blocks = n4 / TILE;
    if (full_blocks > 0) {
        fma_stream_kernel<<<(unsigned)full_blocks, THREADS>>>(
            (const float4*)in, (float4*)out);
    }
    long long done = full_blocks * (long long)TILE * 4;  // elements handled
    long long tail = n - done;
    if (tail > 0) {
        fma_tail_kernel<<<(unsigned)((tail + 255) / 256), 256>>>(
            in, out, done, n);
    }
}